// round 2
// baseline (speedup 1.0000x reference)
#include <cuda_runtime.h>

#define BSZ 2
#define DOP 32
#define RAN 128
#define AZI 128
#define ELE 32
#define NVOX (RAN*AZI*ELE)        /* 524288 */
#define TOTALV (BSZ*NVOX)         /* 1048576 */
#define MAIN_THREADS 256
#define MAIN_BLOCKS (TOTALV/4/MAIN_THREADS)   /* 1024 */

__device__ float g_xyz[BSZ*3*NVOX];
__device__ float g_partials[MAIN_BLOCKS];

// ---------------------------------------------------------------------------
// Kernel 1: precompute xyz volume from coords (B,3,D,H,W)
// ---------------------------------------------------------------------------
__global__ __launch_bounds__(256) void xyz_kernel(const float* __restrict__ coords) {
    int t = blockIdx.x * blockDim.x + threadIdx.x;     // 0 .. TOTALV/4-1
    int g = t * 4;
    int b = g >> 19;                                   // /NVOX
    int n = g & (NVOX - 1);
    const float* cb = coords + (size_t)b * 3 * NVOX;
    float4 r4 = *(const float4*)(cb + n);
    float4 a4 = *(const float4*)(cb + NVOX + n);
    float4 e4 = *(const float4*)(cb + 2 * NVOX + n);
    float rr[4] = {r4.x, r4.y, r4.z, r4.w};
    float aa[4] = {a4.x, a4.y, a4.z, a4.w};
    float ee[4] = {e4.x, e4.y, e4.z, e4.w};
    float xo[4], yo[4], zo[4];
#pragma unroll
    for (int j = 0; j < 4; j++) {
        float sa, ca, se, ce;
        __sincosf(aa[j], &sa, &ca);
        __sincosf(ee[j], &se, &ce);
        float rce = rr[j] * ce;
        xo[j] = rce * ca;
        yo[j] = rce * sa;
        zo[j] = rr[j] * se;
    }
    float* ob = g_xyz + (size_t)b * 3 * NVOX;
    *(float4*)(ob + n)            = make_float4(xo[0], xo[1], xo[2], xo[3]);
    *(float4*)(ob + NVOX + n)     = make_float4(yo[0], yo[1], yo[2], yo[3]);
    *(float4*)(ob + 2*NVOX + n)   = make_float4(zo[0], zo[1], zo[2], zo[3]);
}

// ---------------------------------------------------------------------------
// Kernel 2: fused dop reduction + trilinear warp + loss partial sums
// ---------------------------------------------------------------------------
__device__ __forceinline__ float fsig(float x) {
    return 1.0f / (1.0f + __expf(-x));
}

__global__ __launch_bounds__(MAIN_THREADS) void main_kernel(
    const float* __restrict__ seg,
    const float* __restrict__ flow,
    const float* __restrict__ x1,
    const float* __restrict__ dop_arr,
    const float* __restrict__ ori,
    const float* __restrict__ gumbels)
{
    __shared__ float s_dop[DOP];
    __shared__ float s_red[MAIN_THREADS / 32];

    int t = blockIdx.x * blockDim.x + threadIdx.x;
    int g = t * 4;
    int b = g >> 19;
    int n = g & (NVOX - 1);

    if (threadIdx.x < DOP) s_dop[threadIdx.x] = dop_arr[b * DOP + threadIdx.x];
    __syncthreads();

    // ---- dop-axis pass: softmax weighted sum + argmax(x1+gumbel) ----
    const float* x1p = x1      + (size_t)b * DOP * NVOX + n;
    const float* gp  = gumbels + (size_t)b * DOP * NVOX + n;

    float sume[4]  = {0.f, 0.f, 0.f, 0.f};
    float wsum[4]  = {0.f, 0.f, 0.f, 0.f};
    float best[4]  = {-1e30f, -1e30f, -1e30f, -1e30f};
    float bestd[4] = {0.f, 0.f, 0.f, 0.f};

#pragma unroll 4
    for (int d = 0; d < DOP; d++) {
        float4 xv = *(const float4*)(x1p + (size_t)d * NVOX);
        float4 gv = *(const float4*)(gp  + (size_t)d * NVOX);
        float dv = s_dop[d];
        float xs[4] = {xv.x, xv.y, xv.z, xv.w};
        float gs[4] = {gv.x, gv.y, gv.z, gv.w};
#pragma unroll
        for (int j = 0; j < 4; j++) {
            float ev = __expf(xs[j]);
            sume[j] += ev;
            wsum[j] += ev * dv;
            float key = xs[j] + gs[j];
            if (key > best[j]) { best[j] = key; bestd[j] = dv; }
        }
    }

    // ---- per-voxel data (vectorized) ----
    const float* fp = flow + (size_t)(b * NVOX + n) * 3;
    float4 fA = *(const float4*)(fp);
    float4 fB = *(const float4*)(fp + 4);
    float4 fC = *(const float4*)(fp + 8);
    float f[12] = {fA.x, fA.y, fA.z, fA.w, fB.x, fB.y, fB.z, fB.w,
                   fC.x, fC.y, fC.z, fC.w};

    const float* xb = g_xyz + (size_t)b * 3 * NVOX;
    float4 ox4 = *(const float4*)(xb + n);
    float4 oy4 = *(const float4*)(xb + NVOX + n);
    float4 oz4 = *(const float4*)(xb + 2 * NVOX + n);
    float ox[4] = {ox4.x, ox4.y, ox4.z, ox4.w};
    float oy[4] = {oy4.x, oy4.y, oy4.z, oy4.w};
    float oz[4] = {oz4.x, oz4.y, oz4.z, oz4.w};

    const float* ob = ori + (size_t)b * 3 * NVOX;
    float4 r0 = *(const float4*)(ob + n);
    float4 r1 = *(const float4*)(ob + NVOX + n);
    float4 r2 = *(const float4*)(ob + 2 * NVOX + n);
    float o0[4] = {r0.x, r0.y, r0.z, r0.w};
    float o1[4] = {r1.x, r1.y, r1.z, r1.w};
    float o2[4] = {r2.x, r2.y, r2.z, r2.w};

    float4 sg4 = *(const float4*)(seg + (size_t)b * NVOX + n);
    float sg[4] = {sg4.x, sg4.y, sg4.z, sg4.w};

    float acc = 0.f;
#pragma unroll
    for (int j = 0; j < 4; j++) {
        int nn = n + j;
        int ei = nn & 31;
        int ai = (nn >> 5) & 127;
        int ri = nn >> 12;

        float ixf = fminf(fmaxf((float)ei + f[3*j + 0], 0.f), 31.f);
        float iyf = fminf(fmaxf((float)ai + f[3*j + 1], 0.f), 127.f);
        float izf = fminf(fmaxf((float)ri + f[3*j + 2], 0.f), 127.f);

        int x0 = (int)ixf;  float wx = ixf - (float)x0;  int x1i = min(x0 + 1, 31);
        int y0 = (int)iyf;  float wy = iyf - (float)y0;  int y1i = min(y0 + 1, 127);
        int z0 = (int)izf;  float wz = izf - (float)z0;  int z1i = min(z0 + 1, 127);

        float sxv = 0.f, syv = 0.f, szv = 0.f;
#pragma unroll
        for (int c = 0; c < 8; c++) {
            int   zz  = (c & 4) ? z1i : z0;
            float wzz = (c & 4) ? wz  : 1.f - wz;
            int   yy  = (c & 2) ? y1i : y0;
            float wyy = (c & 2) ? wy  : 1.f - wy;
            int   xx  = (c & 1) ? x1i : x0;
            float wxx = (c & 1) ? wx  : 1.f - wx;
            float w = wzz * wyy * wxx;
            int idx = (zz * AZI + yy) * ELE + xx;
            sxv += w * xb[idx];
            syv += w * xb[NVOX + idx];
            szv += w * xb[2 * NVOX + idx];
        }

        float vx = (sxv - ox[j]) * 10.f;   // / INTERVAL(0.1)
        float vy = (syv - oy[j]) * 10.f;
        float vz = (szv - oz[j]) * 10.f;
        float lab = vx * o0[j] + vy * o1[j] + vz * o2[j];

        float d1 = lab - bestd[j];              d1 *= d1;
        float d2 = lab - wsum[j] / sume[j];     d2 *= d2;
        float s1 = fsig(10.f * (0.15f - d1));
        float s2 = fsig(10.f * (0.15f - d2));
        float sl = 0.5f * (s1 + s2);
        float ss = fsig(sg[j]);
        acc += fabsf(ss - sl);
    }

    // ---- deterministic per-block reduction ----
#pragma unroll
    for (int o = 16; o; o >>= 1) acc += __shfl_xor_sync(0xffffffffu, acc, o);
    if ((threadIdx.x & 31) == 0) s_red[threadIdx.x >> 5] = acc;
    __syncthreads();
    if (threadIdx.x < (MAIN_THREADS / 32)) {
        float v = s_red[threadIdx.x];
#pragma unroll
        for (int o = (MAIN_THREADS / 64); o; o >>= 1)
            v += __shfl_xor_sync(0xffffffffu, v, o);
        if (threadIdx.x == 0) g_partials[blockIdx.x] = v;
    }
}

// ---------------------------------------------------------------------------
// Kernel 3: final reduction of block partials -> scalar mean
// ---------------------------------------------------------------------------
__global__ __launch_bounds__(256) void final_kernel(float* __restrict__ out) {
    __shared__ float s_red[8];
    float v = 0.f;
    for (int i = threadIdx.x; i < MAIN_BLOCKS; i += 256) v += g_partials[i];
#pragma unroll
    for (int o = 16; o; o >>= 1) v += __shfl_xor_sync(0xffffffffu, v, o);
    if ((threadIdx.x & 31) == 0) s_red[threadIdx.x >> 5] = v;
    __syncthreads();
    if (threadIdx.x < 8) {
        float w = s_red[threadIdx.x];
#pragma unroll
        for (int o = 4; o; o >>= 1) w += __shfl_xor_sync(0xffu, w, o);
        if (threadIdx.x == 0) out[0] = w * (1.0f / (float)TOTALV);
    }
}

// ---------------------------------------------------------------------------
// Inputs (metadata order): seg, flow, x1, dop_arr, coords, ori, gumbels
// ---------------------------------------------------------------------------
extern "C" void kernel_launch(void* const* d_in, const int* in_sizes, int n_in,
                              void* d_out, int out_size) {
    const float* seg     = (const float*)d_in[0];
    const float* flow    = (const float*)d_in[1];
    const float* x1      = (const float*)d_in[2];
    const float* dop_arr = (const float*)d_in[3];
    const float* coords  = (const float*)d_in[4];
    const float* ori     = (const float*)d_in[5];
    const float* gumbels = (const float*)d_in[6];
    float* out = (float*)d_out;

    xyz_kernel<<<TOTALV / 4 / 256, 256>>>(coords);
    main_kernel<<<MAIN_BLOCKS, MAIN_THREADS>>>(seg, flow, x1, dop_arr, ori, gumbels);
    final_kernel<<<1, 256>>>(out);
}

// round 3
// speedup vs baseline: 1.0258x; 1.0258x over previous
#include <cuda_runtime.h>

#define BSZ 2
#define DOP 32
#define RAN 128
#define AZI 128
#define ELE 32
#define NVOX (RAN*AZI*ELE)        /* 524288 */
#define TOTALV (BSZ*NVOX)         /* 1048576 */

#define DOPK_THREADS 512
#define DOPK_BLOCKS (TOTALV/4/DOPK_THREADS)    /* 512 */
#define GATK_THREADS 256
#define GATK_BLOCKS (TOTALV/4/GATK_THREADS)    /* 1024 */

__device__ float4 g_xyz4[TOTALV];              /* interleaved (x,y,z,0): 16MB */
__device__ float  g_dop1[TOTALV];              /* argmax-selected dop value */
__device__ float  g_dop2[TOTALV];              /* softmax-weighted dop value */
__device__ float  g_partials[GATK_BLOCKS];

// ---------------------------------------------------------------------------
// Kernel 1: precompute xyz volume (interleaved float4) from coords (B,3,D,H,W)
// ---------------------------------------------------------------------------
__global__ __launch_bounds__(256) void xyz_kernel(const float* __restrict__ coords) {
    int t = blockIdx.x * blockDim.x + threadIdx.x;     // 0 .. TOTALV/4-1
    int g = t * 4;
    int b = g >> 19;
    int n = g & (NVOX - 1);
    const float* cb = coords + (size_t)b * 3 * NVOX;
    float4 r4 = *(const float4*)(cb + n);
    float4 a4 = *(const float4*)(cb + NVOX + n);
    float4 e4 = *(const float4*)(cb + 2 * NVOX + n);
    float rr[4] = {r4.x, r4.y, r4.z, r4.w};
    float aa[4] = {a4.x, a4.y, a4.z, a4.w};
    float ee[4] = {e4.x, e4.y, e4.z, e4.w};
    float4* ob = g_xyz4 + (size_t)b * NVOX + n;
#pragma unroll
    for (int j = 0; j < 4; j++) {
        float sa, ca, se, ce;
        __sincosf(aa[j], &sa, &ca);
        __sincosf(ee[j], &se, &ce);
        float rce = rr[j] * ce;
        ob[j] = make_float4(rce * ca, rce * sa, rr[j] * se, 0.0f);
    }
}

// ---------------------------------------------------------------------------
// Kernel 2: pure streaming dop pass over x1 + gumbels (268 MB)
//   dop1 = dop_arr[argmax_d(x1+gumbel)]
//   dop2 = sum_d softmax(x1)_d * dop_arr[d]
// ---------------------------------------------------------------------------
__global__ __launch_bounds__(DOPK_THREADS) void dop_kernel(
    const float* __restrict__ x1,
    const float* __restrict__ gumbels,
    const float* __restrict__ dop_arr)
{
    __shared__ float s_dop[DOP];
    int t = blockIdx.x * blockDim.x + threadIdx.x;
    int g = t * 4;
    int b = g >> 19;
    int n = g & (NVOX - 1);

    if (threadIdx.x < DOP) s_dop[threadIdx.x] = dop_arr[b * DOP + threadIdx.x];
    __syncthreads();

    const float* x1p = x1      + (size_t)b * DOP * NVOX + n;
    const float* gp  = gumbels + (size_t)b * DOP * NVOX + n;

    float sume[4]  = {0.f, 0.f, 0.f, 0.f};
    float wsum[4]  = {0.f, 0.f, 0.f, 0.f};
    float best[4]  = {-1e30f, -1e30f, -1e30f, -1e30f};
    float bestd[4] = {0.f, 0.f, 0.f, 0.f};

#pragma unroll 8
    for (int d = 0; d < DOP; d++) {
        float4 xv = *(const float4*)(x1p + (size_t)d * NVOX);
        float4 gv = *(const float4*)(gp  + (size_t)d * NVOX);
        float dv = s_dop[d];
        float xs[4] = {xv.x, xv.y, xv.z, xv.w};
        float gs[4] = {gv.x, gv.y, gv.z, gv.w};
#pragma unroll
        for (int j = 0; j < 4; j++) {
            float ev = __expf(xs[j]);
            sume[j] += ev;
            wsum[j] += ev * dv;
            float key = xs[j] + gs[j];
            if (key > best[j]) { best[j] = key; bestd[j] = dv; }
        }
    }

    int o = b * NVOX + n;
    *(float4*)(g_dop1 + o) = make_float4(bestd[0], bestd[1], bestd[2], bestd[3]);
    *(float4*)(g_dop2 + o) = make_float4(wsum[0] / sume[0], wsum[1] / sume[1],
                                         wsum[2] / sume[2], wsum[3] / sume[3]);
}

// ---------------------------------------------------------------------------
// Kernel 3: trilinear warp gather + loss partial sums
// ---------------------------------------------------------------------------
__device__ __forceinline__ float fsig(float x) {
    return 1.0f / (1.0f + __expf(-x));
}

__global__ __launch_bounds__(GATK_THREADS) void gather_kernel(
    const float* __restrict__ seg,
    const float* __restrict__ flow,
    const float* __restrict__ ori)
{
    __shared__ float s_red[GATK_THREADS / 32];

    int t = blockIdx.x * blockDim.x + threadIdx.x;
    int g = t * 4;
    int b = g >> 19;
    int n = g & (NVOX - 1);

    const float* fp = flow + (size_t)(b * NVOX + n) * 3;
    float4 fA = *(const float4*)(fp);
    float4 fB = *(const float4*)(fp + 4);
    float4 fC = *(const float4*)(fp + 8);
    float f[12] = {fA.x, fA.y, fA.z, fA.w, fB.x, fB.y, fB.z, fB.w,
                   fC.x, fC.y, fC.z, fC.w};

    const float4* xb = g_xyz4 + (size_t)b * NVOX;

    const float* ob = ori + (size_t)b * 3 * NVOX;
    float4 r0 = *(const float4*)(ob + n);
    float4 r1 = *(const float4*)(ob + NVOX + n);
    float4 r2 = *(const float4*)(ob + 2 * NVOX + n);
    float o0[4] = {r0.x, r0.y, r0.z, r0.w};
    float o1[4] = {r1.x, r1.y, r1.z, r1.w};
    float o2[4] = {r2.x, r2.y, r2.z, r2.w};

    float4 sg4 = *(const float4*)(seg + (size_t)b * NVOX + n);
    float sg[4] = {sg4.x, sg4.y, sg4.z, sg4.w};

    float4 d14 = *(const float4*)(g_dop1 + b * NVOX + n);
    float4 d24 = *(const float4*)(g_dop2 + b * NVOX + n);
    float dd1[4] = {d14.x, d14.y, d14.z, d14.w};
    float dd2[4] = {d24.x, d24.y, d24.z, d24.w};

    float acc = 0.f;
#pragma unroll
    for (int j = 0; j < 4; j++) {
        int nn = n + j;
        int ei = nn & 31;
        int ai = (nn >> 5) & 127;
        int ri = nn >> 12;

        float ixf = fminf(fmaxf((float)ei + f[3*j + 0], 0.f), 31.f);
        float iyf = fminf(fmaxf((float)ai + f[3*j + 1], 0.f), 127.f);
        float izf = fminf(fmaxf((float)ri + f[3*j + 2], 0.f), 127.f);

        int x0 = (int)ixf;  float wx = ixf - (float)x0;  int x1i = min(x0 + 1, 31);
        int y0 = (int)iyf;  float wy = iyf - (float)y0;  int y1i = min(y0 + 1, 127);
        int z0 = (int)izf;  float wz = izf - (float)z0;  int z1i = min(z0 + 1, 127);

        float sxv = 0.f, syv = 0.f, szv = 0.f;
#pragma unroll
        for (int c = 0; c < 8; c++) {
            int   zz  = (c & 4) ? z1i : z0;
            float wzz = (c & 4) ? wz  : 1.f - wz;
            int   yy  = (c & 2) ? y1i : y0;
            float wyy = (c & 2) ? wy  : 1.f - wy;
            int   xx  = (c & 1) ? x1i : x0;
            float wxx = (c & 1) ? wx  : 1.f - wx;
            float w = wzz * wyy * wxx;
            float4 v = __ldg(xb + (zz * AZI + yy) * ELE + xx);
            sxv += w * v.x;
            syv += w * v.y;
            szv += w * v.z;
        }

        float4 own = xb[nn];
        float vx = (sxv - own.x) * 10.f;   // / INTERVAL(0.1)
        float vy = (syv - own.y) * 10.f;
        float vz = (szv - own.z) * 10.f;
        float lab = vx * o0[j] + vy * o1[j] + vz * o2[j];

        float d1 = lab - dd1[j];   d1 *= d1;
        float d2 = lab - dd2[j];   d2 *= d2;
        float s1 = fsig(10.f * (0.15f - d1));
        float s2 = fsig(10.f * (0.15f - d2));
        float sl = 0.5f * (s1 + s2);
        float ss = fsig(sg[j]);
        acc += fabsf(ss - sl);
    }

    // ---- deterministic per-block reduction ----
#pragma unroll
    for (int o = 16; o; o >>= 1) acc += __shfl_xor_sync(0xffffffffu, acc, o);
    if ((threadIdx.x & 31) == 0) s_red[threadIdx.x >> 5] = acc;
    __syncthreads();
    if (threadIdx.x < (GATK_THREADS / 32)) {
        float v = s_red[threadIdx.x];
#pragma unroll
        for (int o = (GATK_THREADS / 64); o; o >>= 1)
            v += __shfl_xor_sync(0xffffffffu, v, o);
        if (threadIdx.x == 0) g_partials[blockIdx.x] = v;
    }
}

// ---------------------------------------------------------------------------
// Kernel 4: final reduction of block partials -> scalar mean
// ---------------------------------------------------------------------------
__global__ __launch_bounds__(256) void final_kernel(float* __restrict__ out) {
    __shared__ float s_red[8];
    float v = 0.f;
    for (int i = threadIdx.x; i < GATK_BLOCKS; i += 256) v += g_partials[i];
#pragma unroll
    for (int o = 16; o; o >>= 1) v += __shfl_xor_sync(0xffffffffu, v, o);
    if ((threadIdx.x & 31) == 0) s_red[threadIdx.x >> 5] = v;
    __syncthreads();
    if (threadIdx.x < 8) {
        float w = s_red[threadIdx.x];
#pragma unroll
        for (int o = 4; o; o >>= 1) w += __shfl_xor_sync(0xffu, w, o);
        if (threadIdx.x == 0) out[0] = w * (1.0f / (float)TOTALV);
    }
}

// ---------------------------------------------------------------------------
// Inputs (metadata order): seg, flow, x1, dop_arr, coords, ori, gumbels
// ---------------------------------------------------------------------------
extern "C" void kernel_launch(void* const* d_in, const int* in_sizes, int n_in,
                              void* d_out, int out_size) {
    const float* seg     = (const float*)d_in[0];
    const float* flow    = (const float*)d_in[1];
    const float* x1      = (const float*)d_in[2];
    const float* dop_arr = (const float*)d_in[3];
    const float* coords  = (const float*)d_in[4];
    const float* ori     = (const float*)d_in[5];
    const float* gumbels = (const float*)d_in[6];
    float* out = (float*)d_out;

    xyz_kernel<<<TOTALV / 4 / 256, 256>>>(coords);
    dop_kernel<<<DOPK_BLOCKS, DOPK_THREADS>>>(x1, gumbels, dop_arr);
    gather_kernel<<<GATK_BLOCKS, GATK_THREADS>>>(seg, flow, ori);
    final_kernel<<<1, 256>>>(out);
}

// round 7
// speedup vs baseline: 1.2040x; 1.1737x over previous
#include <cuda_runtime.h>

#define BSZ 2
#define DOP 32
#define RAN 128
#define AZI 128
#define ELE 32
#define NVOX (RAN*AZI*ELE)        /* 524288 */
#define TOTALV (BSZ*NVOX)         /* 1048576 */

#define DOPK_THREADS 256
#define DOPK_VPT 2
#define DOPK_BLOCKS (TOTALV/DOPK_VPT/DOPK_THREADS)   /* 2048 */
#define GATK_THREADS 256
#define GATK_BLOCKS (TOTALV/4/GATK_THREADS)          /* 1024 */

__device__ float4 g_xyz4[TOTALV];              /* interleaved (x,y,z,0): 16MB */
__device__ float  g_dop1[TOTALV];
__device__ float  g_dop2[TOTALV];
__device__ float  g_partials[GATK_BLOCKS];

// ---------------------------------------------------------------------------
// Kernel 1: xyz precompute (prologue) + streaming dop pass
// ---------------------------------------------------------------------------
__global__ __launch_bounds__(DOPK_THREADS) void dop_kernel(
    const float* __restrict__ x1,
    const float* __restrict__ gumbels,
    const float* __restrict__ dop_arr,
    const float* __restrict__ coords)
{
    __shared__ float s_dop[DOP];
    int t = blockIdx.x * blockDim.x + threadIdx.x;
    int g = t * DOPK_VPT;
    int b = g >> 19;
    int n = g & (NVOX - 1);

    if (threadIdx.x < DOP) s_dop[threadIdx.x] = dop_arr[b * DOP + threadIdx.x];

    // ---- xyz prologue (independent of s_dop) ----
    {
        const float* cb = coords + (size_t)b * 3 * NVOX;
        float2 r2 = *(const float2*)(cb + n);
        float2 a2 = *(const float2*)(cb + NVOX + n);
        float2 e2 = *(const float2*)(cb + 2 * NVOX + n);
        float rr[2] = {r2.x, r2.y};
        float aa[2] = {a2.x, a2.y};
        float ee[2] = {e2.x, e2.y};
        float4* ob = g_xyz4 + (size_t)b * NVOX + n;
#pragma unroll
        for (int j = 0; j < 2; j++) {
            float sa, ca, se, ce;
            __sincosf(aa[j], &sa, &ca);
            __sincosf(ee[j], &se, &ce);
            float rce = rr[j] * ce;
            ob[j] = make_float4(rce * ca, rce * sa, rr[j] * se, 0.0f);
        }
    }
    __syncthreads();

    const float* x1p = x1      + (size_t)b * DOP * NVOX + n;
    const float* gp  = gumbels + (size_t)b * DOP * NVOX + n;

    float sume[2]  = {0.f, 0.f};
    float wsum[2]  = {0.f, 0.f};
    float best[2]  = {-1e30f, -1e30f};
    float bestd[2] = {0.f, 0.f};

#pragma unroll 8
    for (int d = 0; d < DOP; d++) {
        float2 xv = __ldcs((const float2*)(x1p + (size_t)d * NVOX));
        float2 gv = __ldcs((const float2*)(gp  + (size_t)d * NVOX));
        float dv = s_dop[d];
        float xs[2] = {xv.x, xv.y};
        float gs[2] = {gv.x, gv.y};
#pragma unroll
        for (int j = 0; j < 2; j++) {
            float ev = __expf(xs[j]);
            sume[j] += ev;
            wsum[j] += ev * dv;
            float key = xs[j] + gs[j];
            if (key > best[j]) { best[j] = key; bestd[j] = dv; }
        }
    }

    int o = b * NVOX + n;
    *(float2*)(g_dop1 + o) = make_float2(bestd[0], bestd[1]);
    *(float2*)(g_dop2 + o) = make_float2(wsum[0] / sume[0], wsum[1] / sume[1]);
}

// ---------------------------------------------------------------------------
// Kernel 2: trilinear warp gather + loss partial sums
// ---------------------------------------------------------------------------
__device__ __forceinline__ float fsig(float x) {
    return 1.0f / (1.0f + __expf(-x));
}

__global__ __launch_bounds__(GATK_THREADS) void gather_kernel(
    const float* __restrict__ seg,
    const float* __restrict__ flow,
    const float* __restrict__ ori)
{
    __shared__ float s_red[GATK_THREADS / 32];

    int t = blockIdx.x * blockDim.x + threadIdx.x;
    int g = t * 4;
    int b = g >> 19;
    int n = g & (NVOX - 1);

    const float* fp = flow + (size_t)(b * NVOX + n) * 3;
    float4 fA = *(const float4*)(fp);
    float4 fB = *(const float4*)(fp + 4);
    float4 fC = *(const float4*)(fp + 8);
    float f[12] = {fA.x, fA.y, fA.z, fA.w, fB.x, fB.y, fB.z, fB.w,
                   fC.x, fC.y, fC.z, fC.w};

    const float4* xb = g_xyz4 + (size_t)b * NVOX;

    const float* ob = ori + (size_t)b * 3 * NVOX;
    float4 r0 = *(const float4*)(ob + n);
    float4 r1 = *(const float4*)(ob + NVOX + n);
    float4 r2 = *(const float4*)(ob + 2 * NVOX + n);
    float o0[4] = {r0.x, r0.y, r0.z, r0.w};
    float o1[4] = {r1.x, r1.y, r1.z, r1.w};
    float o2[4] = {r2.x, r2.y, r2.z, r2.w};

    float4 sg4 = *(const float4*)(seg + (size_t)b * NVOX + n);
    float sg[4] = {sg4.x, sg4.y, sg4.z, sg4.w};

    float4 d14 = *(const float4*)(g_dop1 + b * NVOX + n);
    float4 d24 = *(const float4*)(g_dop2 + b * NVOX + n);
    float dd1[4] = {d14.x, d14.y, d14.z, d14.w};
    float dd2[4] = {d24.x, d24.y, d24.z, d24.w};

    float acc = 0.f;
#pragma unroll
    for (int j = 0; j < 4; j++) {
        int nn = n + j;
        int ei = nn & 31;
        int ai = (nn >> 5) & 127;
        int ri = nn >> 12;

        float ixf = fminf(fmaxf((float)ei + f[3*j + 0], 0.f), 31.f);
        float iyf = fminf(fmaxf((float)ai + f[3*j + 1], 0.f), 127.f);
        float izf = fminf(fmaxf((float)ri + f[3*j + 2], 0.f), 127.f);

        int x0 = (int)ixf;  float wx = ixf - (float)x0;  int x1i = min(x0 + 1, 31);
        int y0 = (int)iyf;  float wy = iyf - (float)y0;  int y1i = min(y0 + 1, 127);
        int z0 = (int)izf;  float wz = izf - (float)z0;  int z1i = min(z0 + 1, 127);

        float sxv = 0.f, syv = 0.f, szv = 0.f;
#pragma unroll
        for (int c = 0; c < 8; c++) {
            int   zz  = (c & 4) ? z1i : z0;
            float wzz = (c & 4) ? wz  : 1.f - wz;
            int   yy  = (c & 2) ? y1i : y0;
            float wyy = (c & 2) ? wy  : 1.f - wy;
            int   xx  = (c & 1) ? x1i : x0;
            float wxx = (c & 1) ? wx  : 1.f - wx;
            float w = wzz * wyy * wxx;
            float4 v = __ldg(xb + (zz * AZI + yy) * ELE + xx);
            sxv += w * v.x;
            syv += w * v.y;
            szv += w * v.z;
        }

        float4 own = xb[nn];
        float vx = (sxv - own.x) * 10.f;   // / INTERVAL(0.1)
        float vy = (syv - own.y) * 10.f;
        float vz = (szv - own.z) * 10.f;
        float lab = vx * o0[j] + vy * o1[j] + vz * o2[j];

        float d1 = lab - dd1[j];   d1 *= d1;
        float d2 = lab - dd2[j];   d2 *= d2;
        float s1 = fsig(10.f * (0.15f - d1));
        float s2 = fsig(10.f * (0.15f - d2));
        float sl = 0.5f * (s1 + s2);
        float ss = fsig(sg[j]);
        acc += fabsf(ss - sl);
    }

    // ---- deterministic per-block reduction (exact masks) ----
#pragma unroll
    for (int o = 16; o; o >>= 1) acc += __shfl_xor_sync(0xffffffffu, acc, o);
    if ((threadIdx.x & 31) == 0) s_red[threadIdx.x >> 5] = acc;
    __syncthreads();
    if (threadIdx.x < 32) {
        float v = (threadIdx.x < (GATK_THREADS / 32)) ? s_red[threadIdx.x] : 0.f;
#pragma unroll
        for (int o = 4; o; o >>= 1) v += __shfl_xor_sync(0xffffffffu, v, o);
        if (threadIdx.x == 0) g_partials[blockIdx.x] = v;
    }
}

// ---------------------------------------------------------------------------
// Kernel 3: final reduction of block partials -> scalar mean
// ---------------------------------------------------------------------------
__global__ __launch_bounds__(256) void final_kernel(float* __restrict__ out) {
    __shared__ float s_red[8];
    float v = 0.f;
    for (int i = threadIdx.x; i < GATK_BLOCKS; i += 256) v += g_partials[i];
#pragma unroll
    for (int o = 16; o; o >>= 1) v += __shfl_xor_sync(0xffffffffu, v, o);
    if ((threadIdx.x & 31) == 0) s_red[threadIdx.x >> 5] = v;
    __syncthreads();
    if (threadIdx.x < 32) {
        float w = (threadIdx.x < 8) ? s_red[threadIdx.x] : 0.f;
#pragma unroll
        for (int o = 4; o; o >>= 1) w += __shfl_xor_sync(0xffffffffu, w, o);
        if (threadIdx.x == 0) out[0] = w * (1.0f / (float)TOTALV);
    }
}

// ---------------------------------------------------------------------------
// Inputs (metadata order): seg, flow, x1, dop_arr, coords, ori, gumbels
// ---------------------------------------------------------------------------
extern "C" void kernel_launch(void* const* d_in, const int* in_sizes, int n_in,
                              void* d_out, int out_size) {
    const float* seg     = (const float*)d_in[0];
    const float* flow    = (const float*)d_in[1];
    const float* x1      = (const float*)d_in[2];
    const float* dop_arr = (const float*)d_in[3];
    const float* coords  = (const float*)d_in[4];
    const float* ori     = (const float*)d_in[5];
    const float* gumbels = (const float*)d_in[6];
    float* out = (float*)d_out;

    dop_kernel<<<DOPK_BLOCKS, DOPK_THREADS>>>(x1, gumbels, dop_arr, coords);
    gather_kernel<<<GATK_BLOCKS, GATK_THREADS>>>(seg, flow, ori);
    final_kernel<<<1, 256>>>(out);
}